// round 15
// baseline (speedup 1.0000x reference)
#include <cuda_runtime.h>
#include <cuda_fp16.h>
#include <cstdint>

// Problem constants
// u_t    [16,3,32,32]  f32   d_in[0]
// h_prev [16,9,128,64,64] f32 d_in[1]
// action [16,2] int32         d_in[2]
// W_u    [128,3,3,3] f32      d_in[3]
// W_h    [128,128,3,3] f32    d_in[4]
// out    [16,9,128,64,64] f32
#define WORLD 64
#define WIN   32
#define CC    128
#define VV    9

// ---- smem layout (per CTA, dynamic): two P planes only ----
// P plane: u64[16 slices][276]  (slice = ks*4+kq; row rc = ry*68+xx, ry 0..3, xx 0..65)
//   u64 = (half2 at ci-pair p = 8ks+kq, half2 at p+4); half2 = (ci=2p, ci=2p+1)
#define PD_BYTES (16*276*8)              // 35328
#define SMEM_TOTAL (2*PD_BYTES)          // 70656  (x3 CTAs = 212KB/SM)

// Scratch (device globals; no allocation allowed)
// g_Wg: [plane 18][sl 16][ct 8][lq 8] uint4 — per-thread A fragments (one LDG.128 each)
__device__ __align__(16) uint4 g_Wg[18 * 16 * 8 * 8];
// g_h16: [b 16][vyIdx 3][ci-pair 64][y][x] half2 — channel roll baked per vy only
__device__ __align__(16) uint32_t g_h16[48 * 64 * 64 * 64];
__device__ float g_uconv[16 * 128 * 32 * 32];                // [b][co][y][x]

// ---------------- helpers ----------------
__device__ __forceinline__ uint32_t smem_u32(const void* p) {
    uint32_t a;
    asm("{ .reg .u64 t; cvta.to.shared.u64 t, %1; cvt.u32.u64 %0, t; }" : "=r"(a) : "l"(p));
    return a;
}
__device__ __forceinline__ void lds64(uint32_t& lo, uint32_t& hi, uint32_t addr) {
    asm volatile("ld.shared.v2.b32 {%0,%1}, [%2];" : "=r"(lo), "=r"(hi) : "r"(addr));
}
__device__ __forceinline__ void mma_f16(float c[4], const uint4 a, const uint32_t b0, const uint32_t b1) {
    asm volatile(
        "mma.sync.aligned.m16n8k16.row.col.f32.f16.f16.f32 "
        "{%0,%1,%2,%3}, {%4,%5,%6,%7}, {%8,%9}, {%0,%1,%2,%3};"
        : "+f"(c[0]), "+f"(c[1]), "+f"(c[2]), "+f"(c[3])
        : "r"(a.x), "r"(a.y), "r"(a.z), "r"(a.w), "r"(b0), "r"(b1));
}
__device__ __forceinline__ void cpa4(uint32_t dst, const void* src) {
    asm volatile("cp.async.ca.shared.global [%0], [%1], 4;" :: "r"(dst), "l"(src));
}
__device__ __forceinline__ void cpa_commit() {
    asm volatile("cp.async.commit_group;" ::: "memory");
}
__device__ __forceinline__ void cpa_wait0() {
    asm volatile("cp.async.wait_group 0;" ::: "memory");
}

// ---------- prep: W_h -> per-thread fp16 A-fragment image ----------
// component idx = (((plane*16+sl)*8+ct)*8+lq)*4 + c
// c: co += (c&1)*8 ; ci += (c>>1)*8
__global__ void prep_w_kernel(const float* __restrict__ W_h) {
    int idx = blockIdx.x * blockDim.x + threadIdx.x;
    if (idx >= 18 * 16 * 8 * 8 * 4) return;
    int c     = idx & 3;
    int lq    = (idx >> 2) & 7;
    int ct    = (idx >> 5) & 7;
    int sl    = (idx >> 8) & 15;
    int plane = idx >> 12;            // 0..17 = chunk*9+tap
    int tap   = plane % 9;
    int chunk = plane / 9;
    int ks = sl >> 2, kq = sl & 3;
    int co = ct * 16 + lq + (c & 1) * 8;
    int ci = chunk * 64 + ks * 16 + 2 * kq + (c >> 1) * 8;
    float v0 = W_h[((size_t)co * 128 + ci) * 9 + tap];
    float v1 = W_h[((size_t)co * 128 + ci + 1) * 9 + tap];
    __half2 h = __floats2half2_rn(v0, v1);
    ((uint32_t*)g_Wg)[idx] = *(uint32_t*)&h;
}

// ---------- prep: h_prev -> half2 ci-pair planes, baked per (b, vy) only (3 rolls, not 9) ----------
__global__ void prep_h_kernel(const float* __restrict__ h_prev) {
    size_t idx = (size_t)blockIdx.x * 256 + threadIdx.x;
    if (idx >= (size_t)48 * 64 * 64 * 64) return;
    int xx = idx & 63;
    int gy = (idx >> 6) & 63;
    int p  = (idx >> 12) & 63;
    int bb = idx >> 18;                 // b*3 + vyIdx
    int vyIdx = bb % 3;
    int b     = bb / 3;
    int vy = vyIdx - 1;
    int c0 = (2 * p - vy + 128) & 127;
    int c1 = (2 * p + 1 - vy + 128) & 127;
    // h_prev slice is identical across v for fixed b? NO — h_prev[b, v] differ.
    // Roll is per (b,v); but channel roll amount depends only on vy. We need the
    // per-v data though! g_h16 must stay per (b,v)... see main: it indexes by (b,v).
    // -> This kernel handles ONLY the layout+fp16 pack for the 3 vy variants of each
    //    (b, v) group: pairs sharing vy point at DIFFERENT v slices. So bake per (b,v)
    //    is required after all. Keep per-(b,vy) ONLY valid because main reads
    //    h_prev[b, v] — data differs per v. Hence we must keep v granularity.
    // (dead code guard; real kernel below)
    (void)b; (void)c0; (void)c1; (void)gy; (void)xx;
}

// ---------- prep (actual): h_prev -> half2 ci-pair planes per (b,v) ----------
__global__ void prep_h_kernel2(const float* __restrict__ h_prev,
                               uint32_t* __restrict__ dstall) {
    size_t idx = (size_t)blockIdx.x * 256 + threadIdx.x;
    if (idx >= (size_t)144 * 64 * 64 * 64) return;
    int xx = idx & 63;
    int gy = (idx >> 6) & 63;
    int p  = (idx >> 12) & 63;
    int bv = idx >> 18;                 // b*9+v
    int v  = bv % 9;
    int vy = v % 3 - 1;
    int c0 = (2 * p - vy + 128) & 127;
    int c1 = (2 * p + 1 - vy + 128) & 127;
    const float* hp = h_prev + (size_t)bv * CC * 4096;
    float f0 = hp[(size_t)c0 * 4096 + gy * 64 + xx];
    float f1 = hp[(size_t)c1 * 4096 + gy * 64 + xx];
    __half2 h = __floats2half2_rn(f0, f1);
    dstall[idx] = *(uint32_t*)&h;
}

// ---------- encoder: circular conv u_t * W_u -> g_uconv (exact f32) ----------
__global__ void encoder_kernel(const float* __restrict__ u_t,
                               const float* __restrict__ W_u) {
    int co = blockIdx.x;
    int b  = blockIdx.y;
    __shared__ float us[3 * 32 * 32];
    __shared__ float ws[27];
    int tid = threadIdx.x;
    const float* up = u_t + (size_t)b * 3 * 1024;
    for (int e = tid; e < 3072; e += 256) us[e] = up[e];
    if (tid < 27) ws[tid] = W_u[co * 27 + tid];
    __syncthreads();

    int y  = (tid * 4) >> 5;
    int x0 = (tid * 4) & 31;
    float acc[4] = {0.f, 0.f, 0.f, 0.f};
#pragma unroll
    for (int ci = 0; ci < 3; ++ci)
#pragma unroll
        for (int ky = 0; ky < 3; ++ky) {
            int yy = (y + ky - 1 + 32) & 31;
#pragma unroll
            for (int kx = 0; kx < 3; ++kx) {
                float w = ws[ci * 9 + ky * 3 + kx];
#pragma unroll
                for (int k = 0; k < 4; ++k) {
                    int xx = (x0 + k + kx - 1 + 32) & 31;
                    acc[k] = fmaf(w, us[ci * 1024 + yy * 32 + xx], acc[k]);
                }
            }
        }
    float4 r = {acc[0], acc[1], acc[2], acc[3]};
    *(float4*)&g_uconv[((size_t)(b * 128 + co) * 32 + y) * 32 + x0] = r;
}

// big buffer reused: g_h16 is sized 48*64*64*64 above (50MB) — too small for per-(b,v).
// Use a dedicated full-size buffer:
__device__ __align__(16) uint32_t g_h16full[144 * 64 * 64 * 64];

// ---------- main: fp16 m16n8k16; warp tile co64 x px64 (nt=8); 4 warps/CTA; 3 CTAs/SM ----------
// Block = (2-row tile, v, b); D[co=128][px=128]; warps: wco=wid&1, rl=wid>>1.
__global__ __launch_bounds__(128, 3)
void fernn_f16_kernel(const int* __restrict__ action,
                      float* __restrict__ out) {
    extern __shared__ unsigned char smem[];
    uint32_t sb = smem_u32(smem);

    int tid  = threadIdx.x;
    int wid  = tid >> 5;
    int lane = tid & 31;
    int wco = wid & 1;            // co half (64)
    int rl  = wid >> 1;           // output row in tile (0..1)
    int kq  = lane & 3;
    int lq  = lane >> 2;          // 0..7

    int y0 = blockIdx.x * 2;
    int v  = blockIdx.y;
    int b  = blockIdx.z;

    int ax = action[b * 2 + 0];
    int ay = action[b * 2 + 1];
    int vx = v / 3 - 1;
    // folded index (verified R2): in = h_prev[b,v,(ci-vy)%C,(y+ky-1+Sy)%H,(x+kx-1+Sx)%W]
    // channel roll baked into g_h16full; here only spatial shifts:
    int Sy = ay - vx;
    int Sx = ax;
    const uint32_t* hbase = g_h16full + (size_t)(b * VV + v) * 64 * 4096;

    // ---- P-build mapping: 256 half-row units (p 0..31, ry 0..3, hf 0..1), 33 cols each ----
    int pgy_add = (y0 - 1 + Sy + 128);

    auto issueP = [&](int chunk) {
        uint32_t base = sb + (uint32_t)((chunk & 1) * PD_BYTES);
#pragma unroll
        for (int e0 = 0; e0 < 2; ++e0) {
            int e  = tid + e0 * 128;
            int p  = e >> 3;
            int ry = (e >> 1) & 3;
            int hf = e & 1;
            int ks = p >> 3, rem = p & 7;
            int kqp = rem & 3, phi = rem >> 2;
            uint32_t dst = base
                + (uint32_t)((((ks * 4 + kqp) * 276 + ry * 68) * 2 + phi) * 4)
                + (uint32_t)(hf * 33 * 8);
            int gy = (pgy_add + ry) & 63;
            int gx0 = hf * 33 - 1 + Sx + 64;
            const uint32_t* src = hbase + (size_t)(chunk * 32 + p) * 4096 + gy * 64;
#pragma unroll
            for (int j = 0; j < 33; ++j)
                cpa4(dst + j * 8, src + ((gx0 + j) & 63));
        }
    };

    float acc[4][8][4];
#pragma unroll
    for (int mt = 0; mt < 4; ++mt)
#pragma unroll
        for (int nt = 0; nt < 8; ++nt)
#pragma unroll
            for (int c = 0; c < 4; ++c) acc[mt][nt][c] = 0.f;

    // ---- prologue: P0 async; wait; then issue P1 (overlaps chunk-0 MMAs) ----
    issueP(0);
    cpa_commit();
    cpa_wait0();
    __syncthreads();
    issueP(1);
    cpa_commit();

#pragma unroll 1
    for (int chunk = 0; chunk < 2; ++chunk) {
        uint32_t pbuf = sb + (uint32_t)((chunk & 1) * PD_BYTES);

#pragma unroll 1
        for (int t = 0; t < 9; ++t) {
            int plane = chunk * 9 + t;
            int dy = t / 3;
            int dx = t % 3;
            // B row base: slice sl, row (rl+dy), column (px+dx), px = nt*8+lq
            uint32_t bb = pbuf + (uint32_t)(((rl + dy) * 68 + lq + dx) * 8);
            const uint4* wp = g_Wg + ((size_t)(plane * 16) * 8 + wco * 4) * 8 + lq;

#pragma unroll
            for (int ks = 0; ks < 4; ++ks) {
                int sl = ks * 4 + kq;
                uint4 A[4];
#pragma unroll
                for (int mt = 0; mt < 4; ++mt)
                    A[mt] = __ldg(wp + ((size_t)sl * 8 + mt) * 8);
                uint32_t bbs = bb + (uint32_t)((sl * 276) * 8);
#pragma unroll
                for (int nt = 0; nt < 8; ++nt) {
                    uint32_t B0, B1;
                    lds64(B0, B1, bbs + nt * 64);
#pragma unroll
                    for (int mt = 0; mt < 4; ++mt) mma_f16(acc[mt][nt], A[mt], B0, B1);
                }
            }
        }
        if (chunk == 0) {
            cpa_wait0();     // P1 resident
            __syncthreads();
        }
    }

    // ---- epilogue: +u (top-left window), relu, store ----
    int y = y0 + rl;
    float* obase = out + (size_t)((b * VV + v) * CC) * 4096 + (size_t)y * 64;
    bool rowu = (y < WIN);

#pragma unroll
    for (int mt = 0; mt < 4; ++mt) {
        int co = wco * 64 + mt * 16 + lq;
#pragma unroll
        for (int nt = 0; nt < 8; ++nt) {
            int px = nt * 8 + 2 * kq;
            float2 v0 = {acc[mt][nt][0], acc[mt][nt][1]};
            float2 v1 = {acc[mt][nt][2], acc[mt][nt][3]};
            if (rowu && px < WIN) {
                const float* u0 = g_uconv + (size_t)(b * CC + co) * 1024 + y * 32 + px;
                const float* u1 = g_uconv + (size_t)(b * CC + co + 8) * 1024 + y * 32 + px;
                v0.x += u0[0]; v0.y += u0[1];
                v1.x += u1[0]; v1.y += u1[1];
            }
            v0.x = fmaxf(v0.x, 0.f); v0.y = fmaxf(v0.y, 0.f);
            v1.x = fmaxf(v1.x, 0.f); v1.y = fmaxf(v1.y, 0.f);
            *(float2*)(obase + (size_t)co * 4096 + px)       = v0;
            *(float2*)(obase + (size_t)(co + 8) * 4096 + px) = v1;
        }
    }
}

extern "C" void kernel_launch(void* const* d_in, const int* in_sizes, int n_in,
                              void* d_out, int out_size) {
    const float* u_t    = (const float*)d_in[0];
    const float* h_prev = (const float*)d_in[1];
    const int*   action = (const int*)d_in[2];
    const float* W_u    = (const float*)d_in[3];
    const float* W_h    = (const float*)d_in[4];
    float* out = (float*)d_out;

    cudaFuncSetAttribute(fernn_f16_kernel,
                         cudaFuncAttributeMaxDynamicSharedMemorySize, SMEM_TOTAL);

    uint32_t* h16p = nullptr;
    cudaGetSymbolAddress((void**)&h16p, g_h16full);

    prep_w_kernel<<<(18 * 16 * 8 * 8 * 4 + 255) / 256, 256>>>(W_h);
    prep_h_kernel2<<<(int)(((size_t)144 * 64 * 64 * 64 + 255) / 256), 256>>>(h_prev, h16p);
    encoder_kernel<<<dim3(128, 16), 256>>>(u_t, W_u);
    fernn_f16_kernel<<<dim3(32, 9, 16), 128, SMEM_TOTAL>>>(action, out);
}

// round 16
// speedup vs baseline: 1.4082x; 1.4082x over previous
#include <cuda_runtime.h>
#include <cuda_fp16.h>
#include <cstdint>

// Problem constants
// u_t    [16,3,32,32]  f32   d_in[0]
// h_prev [16,9,128,64,64] f32 d_in[1]
// action [16,2] int32         d_in[2]
// W_u    [128,3,3,3] f32      d_in[3]
// W_h    [128,128,3,3] f32    d_in[4]
// out    [16,9,128,64,64] f32
#define WORLD 64
#define WIN   32
#define CC    128
#define VV    9

// ---- smem layout (per CTA, dynamic): two P planes ----
// P plane: u64[16 slices][420]  (slice = ks*4+kq; row rc = ry*68+xx, ry 0..5, xx 0..65)
//   u64 = (half2 at ci-pair p = 8ks+kq, half2 at p+4); half2 = (ci=2p, ci=2p+1)
// slice stride 420 u64 = 840 words == 8 mod 32 -> B-LDS bank pattern 2*lq+8*kq, conflict-free
#define PD_BYTES (16*420*8)              // 53760
#define SMEM_TOTAL (2*PD_BYTES)          // 107520 (1 CTA of 256 thr per SM)

// Scratch (device globals; no allocation allowed)
// g_Wg: [plane 18][sl 16][ct 8][lq 8] uint4 — per-thread A fragments (one LDG.128 each)
__device__ __align__(16) uint4 g_Wg[18 * 16 * 8 * 8];
__device__ __align__(16) uint32_t g_h16[144 * 64 * 64 * 64]; // [bv][ci-pair][y][x] half2
__device__ float g_uconv[16 * 128 * 32 * 32];                // [b][co][y][x]

// ---------------- helpers ----------------
__device__ __forceinline__ uint32_t smem_u32(const void* p) {
    uint32_t a;
    asm("{ .reg .u64 t; cvta.to.shared.u64 t, %1; cvt.u32.u64 %0, t; }" : "=r"(a) : "l"(p));
    return a;
}
__device__ __forceinline__ void lds64(uint32_t& lo, uint32_t& hi, uint32_t addr) {
    asm volatile("ld.shared.v2.b32 {%0,%1}, [%2];" : "=r"(lo), "=r"(hi) : "r"(addr));
}
__device__ __forceinline__ void mma_f16(float c[4], const uint4 a, const uint32_t b0, const uint32_t b1) {
    asm volatile(
        "mma.sync.aligned.m16n8k16.row.col.f32.f16.f16.f32 "
        "{%0,%1,%2,%3}, {%4,%5,%6,%7}, {%8,%9}, {%0,%1,%2,%3};"
        : "+f"(c[0]), "+f"(c[1]), "+f"(c[2]), "+f"(c[3])
        : "r"(a.x), "r"(a.y), "r"(a.z), "r"(a.w), "r"(b0), "r"(b1));
}
__device__ __forceinline__ void cpa4(uint32_t dst, const void* src) {
    asm volatile("cp.async.ca.shared.global [%0], [%1], 4;" :: "r"(dst), "l"(src));
}
__device__ __forceinline__ void cpa_commit() {
    asm volatile("cp.async.commit_group;" ::: "memory");
}
__device__ __forceinline__ void cpa_wait0() {
    asm volatile("cp.async.wait_group 0;" ::: "memory");
}

// ---------- prep: W_h -> per-thread fp16 A-fragment image ----------
// component idx = (((plane*16+sl)*8+ct)*8+lq)*4 + c
// c: co += (c&1)*8 ; ci += (c>>1)*8
__global__ void prep_w_kernel(const float* __restrict__ W_h) {
    int idx = blockIdx.x * blockDim.x + threadIdx.x;
    if (idx >= 18 * 16 * 8 * 8 * 4) return;
    int c     = idx & 3;
    int lq    = (idx >> 2) & 7;
    int ct    = (idx >> 5) & 7;
    int sl    = (idx >> 8) & 15;
    int plane = idx >> 12;            // 0..17 = chunk*9+tap
    int tap   = plane % 9;
    int chunk = plane / 9;
    int ks = sl >> 2, kq = sl & 3;
    int co = ct * 16 + lq + (c & 1) * 8;
    int ci = chunk * 64 + ks * 16 + 2 * kq + (c >> 1) * 8;
    float v0 = W_h[((size_t)co * 128 + ci) * 9 + tap];
    float v1 = W_h[((size_t)co * 128 + ci + 1) * 9 + tap];
    __half2 h = __floats2half2_rn(v0, v1);
    ((uint32_t*)g_Wg)[idx] = *(uint32_t*)&h;
}

// ---------- prep: h_prev -> half2 ci-pair planes (channel roll baked per (b,v)) ----------
__global__ void prep_h_kernel(const float* __restrict__ h_prev) {
    size_t idx = (size_t)blockIdx.x * 256 + threadIdx.x;
    if (idx >= (size_t)144 * 64 * 64 * 64) return;
    int xx = idx & 63;
    int gy = (idx >> 6) & 63;
    int p  = (idx >> 12) & 63;
    int bv = idx >> 18;                 // b*9+v
    int v  = bv % 9;
    int vy = v % 3 - 1;
    int c0 = (2 * p - vy + 128) & 127;
    int c1 = (2 * p + 1 - vy + 128) & 127;
    const float* hp = h_prev + (size_t)bv * CC * 4096;
    float f0 = hp[(size_t)c0 * 4096 + gy * 64 + xx];
    float f1 = hp[(size_t)c1 * 4096 + gy * 64 + xx];
    __half2 h = __floats2half2_rn(f0, f1);
    g_h16[idx] = *(uint32_t*)&h;
}

// ---------- encoder: circular conv u_t * W_u -> g_uconv (exact f32) ----------
__global__ void encoder_kernel(const float* __restrict__ u_t,
                               const float* __restrict__ W_u) {
    int co = blockIdx.x;
    int b  = blockIdx.y;
    __shared__ float us[3 * 32 * 32];
    __shared__ float ws[27];
    int tid = threadIdx.x;
    const float* up = u_t + (size_t)b * 3 * 1024;
    for (int e = tid; e < 3072; e += 256) us[e] = up[e];
    if (tid < 27) ws[tid] = W_u[co * 27 + tid];
    __syncthreads();

    int y  = (tid * 4) >> 5;
    int x0 = (tid * 4) & 31;
    float acc[4] = {0.f, 0.f, 0.f, 0.f};
#pragma unroll
    for (int ci = 0; ci < 3; ++ci)
#pragma unroll
        for (int ky = 0; ky < 3; ++ky) {
            int yy = (y + ky - 1 + 32) & 31;
#pragma unroll
            for (int kx = 0; kx < 3; ++kx) {
                float w = ws[ci * 9 + ky * 3 + kx];
#pragma unroll
                for (int k = 0; k < 4; ++k) {
                    int xx = (x0 + k + kx - 1 + 32) & 31;
                    acc[k] = fmaf(w, us[ci * 1024 + yy * 32 + xx], acc[k]);
                }
            }
        }
    float4 r = {acc[0], acc[1], acc[2], acc[3]};
    *(float4*)&g_uconv[((size_t)(b * 128 + co) * 32 + y) * 32 + x0] = r;
}

// ---------- main: fp16 m16n8k16; 4-row block tile; 8 warps (wco=wid&1, rl=wid>>1) ----------
// Block = (4-row tile, v, b); D[co=128][px=256]; warp tile co64 x px64; 1 CTA (256 thr)/SM.
__global__ __launch_bounds__(256, 1)
void fernn_f16_kernel(const int* __restrict__ action,
                      float* __restrict__ out) {
    extern __shared__ unsigned char smem[];
    uint32_t sb = smem_u32(smem);

    int tid  = threadIdx.x;
    int wid  = tid >> 5;
    int lane = tid & 31;
    int wco = wid & 1;            // co half (64)
    int rl  = wid >> 1;           // output row in tile (0..3)
    int kq  = lane & 3;
    int lq  = lane >> 2;          // 0..7

    int y0 = blockIdx.x * 4;
    int v  = blockIdx.y;
    int b  = blockIdx.z;

    int ax = action[b * 2 + 0];
    int ay = action[b * 2 + 1];
    int vx = v / 3 - 1;
    // folded index (verified R2): in = h_prev[b,v,(ci-vy)%C,(y+ky-1+Sy)%H,(x+kx-1+Sx)%W]
    // channel roll baked into g_h16; here only spatial shifts:
    int Sy = ay - vx;
    int Sx = ax;
    const uint32_t* hbase = g_h16 + (size_t)(b * VV + v) * 64 * 4096;

    // ---- P-build mapping: 384 half-row units (p 0..31, ry 0..5, hf 0..1), 33 cols each ----
    int pgy_add = (y0 - 1 + Sy + 128);

    auto issueP = [&](int chunk) {
        uint32_t base = sb + (uint32_t)((chunk & 1) * PD_BYTES);
#pragma unroll
        for (int e0 = 0; e0 < 2; ++e0) {
            int e = tid + e0 * 256;
            if (e < 384) {
                int p   = e / 12;
                int rem = e - p * 12;
                int ry  = rem >> 1;
                int hf  = rem & 1;
                int ks = p >> 3, prem = p & 7;
                int kqp = prem & 3, phi = prem >> 2;
                uint32_t dst = base
                    + (uint32_t)((((ks * 4 + kqp) * 420 + ry * 68) * 2 + phi) * 4)
                    + (uint32_t)(hf * 33 * 8);
                int gy = (pgy_add + ry) & 63;
                int gx0 = hf * 33 - 1 + Sx + 64;
                const uint32_t* src = hbase + (size_t)(chunk * 32 + p) * 4096 + gy * 64;
#pragma unroll
                for (int j = 0; j < 33; ++j)
                    cpa4(dst + j * 8, src + ((gx0 + j) & 63));
            }
        }
    };

    float acc[4][8][4];
#pragma unroll
    for (int mt = 0; mt < 4; ++mt)
#pragma unroll
        for (int nt = 0; nt < 8; ++nt)
#pragma unroll
            for (int c = 0; c < 4; ++c) acc[mt][nt][c] = 0.f;

    // ---- prologue: P0 async; wait; then issue P1 (overlaps chunk-0 MMAs) ----
    issueP(0);
    cpa_commit();
    cpa_wait0();
    __syncthreads();
    issueP(1);
    cpa_commit();

#pragma unroll 1
    for (int chunk = 0; chunk < 2; ++chunk) {
        uint32_t pbuf = sb + (uint32_t)((chunk & 1) * PD_BYTES);

#pragma unroll 1
        for (int t = 0; t < 9; ++t) {
            int plane = chunk * 9 + t;
            int dy = t / 3;
            int dx = t % 3;
            // B row base: slice sl, row (rl+dy), column (px+dx), px = nt*8+lq
            uint32_t bb = pbuf + (uint32_t)(((rl + dy) * 68 + lq + dx) * 8);
            const uint4* wp = g_Wg + ((size_t)(plane * 16) * 8 + wco * 4) * 8 + lq;

#pragma unroll
            for (int ks = 0; ks < 4; ++ks) {
                int sl = ks * 4 + kq;
                uint4 A[4];
#pragma unroll
                for (int mt = 0; mt < 4; ++mt)
                    A[mt] = __ldg(wp + ((size_t)sl * 8 + mt) * 8);
                uint32_t bbs = bb + (uint32_t)((sl * 420) * 8);
#pragma unroll
                for (int nt = 0; nt < 8; ++nt) {
                    uint32_t B0, B1;
                    lds64(B0, B1, bbs + nt * 64);
#pragma unroll
                    for (int mt = 0; mt < 4; ++mt) mma_f16(acc[mt][nt], A[mt], B0, B1);
                }
            }
        }
        if (chunk == 0) {
            cpa_wait0();     // P1 resident
            __syncthreads();
        }
    }

    // ---- epilogue: +u (top-left window), relu, store ----
    int y = y0 + rl;
    float* obase = out + (size_t)((b * VV + v) * CC) * 4096 + (size_t)y * 64;
    bool rowu = (y < WIN);

#pragma unroll
    for (int mt = 0; mt < 4; ++mt) {
        int co = wco * 64 + mt * 16 + lq;
#pragma unroll
        for (int nt = 0; nt < 8; ++nt) {
            int px = nt * 8 + 2 * kq;
            float2 v0 = {acc[mt][nt][0], acc[mt][nt][1]};
            float2 v1 = {acc[mt][nt][2], acc[mt][nt][3]};
            if (rowu && px < WIN) {
                const float* u0 = g_uconv + (size_t)(b * CC + co) * 1024 + y * 32 + px;
                const float* u1 = g_uconv + (size_t)(b * CC + co + 8) * 1024 + y * 32 + px;
                v0.x += u0[0]; v0.y += u0[1];
                v1.x += u1[0]; v1.y += u1[1];
            }
            v0.x = fmaxf(v0.x, 0.f); v0.y = fmaxf(v0.y, 0.f);
            v1.x = fmaxf(v1.x, 0.f); v1.y = fmaxf(v1.y, 0.f);
            *(float2*)(obase + (size_t)co * 4096 + px)       = v0;
            *(float2*)(obase + (size_t)(co + 8) * 4096 + px) = v1;
        }
    }
}

extern "C" void kernel_launch(void* const* d_in, const int* in_sizes, int n_in,
                              void* d_out, int out_size) {
    const float* u_t    = (const float*)d_in[0];
    const float* h_prev = (const float*)d_in[1];
    const int*   action = (const int*)d_in[2];
    const float* W_u    = (const float*)d_in[3];
    const float* W_h    = (const float*)d_in[4];
    float* out = (float*)d_out;

    cudaFuncSetAttribute(fernn_f16_kernel,
                         cudaFuncAttributeMaxDynamicSharedMemorySize, SMEM_TOTAL);

    prep_w_kernel<<<(18 * 16 * 8 * 8 * 4 + 255) / 256, 256>>>(W_h);
    prep_h_kernel<<<(int)(((size_t)144 * 64 * 64 * 64 + 255) / 256), 256>>>(h_prev);
    encoder_kernel<<<dim3(128, 16), 256>>>(u_t, W_u);
    fernn_f16_kernel<<<dim3(16, 9, 16), 256, SMEM_TOTAL>>>(action, out);
}